// round 3
// baseline (speedup 1.0000x reference)
#include <cuda_runtime.h>
#include <math.h>

#define B_   32
#define C_   192
#define HH   56
#define WW   56
#define HW   3136      // 56*56
#define CO   384
#define K2   384       // 2*C
#define BN_EPS 1e-5f

// scratch: xj tensor [B, C, H, W] (77 MB)
__device__ float g_xj[(size_t)B_ * C_ * HW];

// ---------------------------------------------------------------------------
// Stage 1: per-(b,c) image -> xj via parity mins.
// xj[p,q] = x[p,q] - min( min over rows r (r&1==p&1) of x[r,q],
//                         min over cols c (c&1==q&1) of x[p,c] )
// (both mins INCLUDE the element itself; this folds the max(0,.) exactly)
// ---------------------------------------------------------------------------
__global__ __launch_bounds__(256) void minxj_kernel(const float* __restrict__ x) {
    __shared__ float img[HW];
    __shared__ float cmin[2][WW];
    __shared__ float rmin[HH][2];
    const size_t bc = blockIdx.x;
    const float* xp = x + bc * HW;
    for (int i = threadIdx.x; i < HW; i += 256) img[i] = xp[i];
    __syncthreads();
    int t = threadIdx.x;
    if (t < 112) {
        int par = t / 56, q = t % 56;
        float m = 3.4e38f;
        #pragma unroll 7
        for (int r = par; r < HH; r += 2) m = fminf(m, img[r * WW + q]);
        cmin[par][q] = m;
    } else if (t < 224) {
        int t2 = t - 112;
        int par = t2 / 56, p = t2 % 56;
        float m = 3.4e38f;
        const float* row = &img[p * WW];
        #pragma unroll 7
        for (int q = par; q < WW; q += 2) m = fminf(m, row[q]);
        rmin[p][par] = m;
    }
    __syncthreads();
    float* xjp = g_xj + bc * HW;
    for (int i = threadIdx.x; i < HW; i += 256) {
        int p = i / WW, q = i - p * WW;
        float v = img[i];
        xjp[i] = v - fminf(cmin[p & 1][q], rmin[p][q & 1]);
    }
}

// ---------------------------------------------------------------------------
// Stage 2: fused per-pixel GEMM + bias + BN(inference) + exact GELU.
// out[b,o,pix] = gelu( (sum_k A[b,pix,k] * Wc[o,k] + bias[o]) * scale + shift )
//   A[:, :192] = x, A[:, 192:] = xj
// Tile: BM=64 pixels x BN=64 outs x BK=16, 256 threads, 4x4 microtile.
// ---------------------------------------------------------------------------
#define BM 64
#define BN 64
#define BK 16

__global__ __launch_bounds__(256) void gemm_bn_gelu_kernel(
    const float* __restrict__ x,  const float* __restrict__ Wc,
    const float* __restrict__ bconv, const float* __restrict__ gamma,
    const float* __restrict__ beta,  const float* __restrict__ rmean,
    const float* __restrict__ rvar,  float* __restrict__ out)
{
    __shared__ float As[BK][BM];
    __shared__ float Bs[BK][BN + 4];   // +4 pad: kills bank conflicts, keeps 16B align

    const int otile = blockIdx.x;          // 0..5
    const int mtile = blockIdx.y % 49;     // 3136/64 = 49 tiles per image (exact)
    const int b     = blockIdx.y / 49;
    const int pix0  = mtile * BM;
    const int o0    = otile * BN;

    const int tid = threadIdx.x;
    const int ty  = tid & 15;    // pixel dim (m = ty*4 + i)
    const int tx  = tid >> 4;    // output-channel dim (o = tx*4 + j)

    float acc[4][4] = {};

    const float* Abase_x  = x    + ((size_t)b * C_) * HW + pix0;
    const float* Abase_xj = g_xj + ((size_t)b * C_) * HW + pix0;

    const int la_m = tid & 63;   // A loader: m
    const int la_k = tid >> 6;   // A loader: k base (0..3), +4 per pass
    const int lb_k = tid & 15;   // B loader: k
    const int lb_o = tid >> 4;   // B loader: o base (0..15), +16 per pass

    for (int kt = 0; kt < K2; kt += BK) {
        #pragma unroll
        for (int pass = 0; pass < 4; pass++) {
            int kl = la_k + pass * 4;
            int ks = kt + kl;
            const float* src = (ks < C_) ? (Abase_x  + (size_t)ks * HW)
                                         : (Abase_xj + (size_t)(ks - C_) * HW);
            As[kl][la_m] = src[la_m];
        }
        #pragma unroll
        for (int pass = 0; pass < 4; pass++) {
            int ol = lb_o + pass * 16;
            Bs[lb_k][ol] = Wc[(size_t)(o0 + ol) * K2 + kt + lb_k];
        }
        __syncthreads();
        #pragma unroll
        for (int kk = 0; kk < BK; kk++) {
            float4 a4 = *(const float4*)&As[kk][ty * 4];
            float4 b4 = *(const float4*)&Bs[kk][tx * 4];
            float av[4] = {a4.x, a4.y, a4.z, a4.w};
            float bv[4] = {b4.x, b4.y, b4.z, b4.w};
            #pragma unroll
            for (int j = 0; j < 4; j++)
                #pragma unroll
                for (int i = 0; i < 4; i++)
                    acc[j][i] = fmaf(av[i], bv[j], acc[j][i]);
        }
        __syncthreads();
    }

    // epilogue: bias + BN fold + exact-erf GELU, vectorized stores
    #pragma unroll
    for (int j = 0; j < 4; j++) {
        const int o = o0 + tx * 4 + j;
        const float sc = gamma[o] * rsqrtf(rvar[o] + BN_EPS);
        const float sh = (bconv[o] - rmean[o]) * sc + beta[o];
        float4 r;
        float ys[4];
        #pragma unroll
        for (int i = 0; i < 4; i++) {
            float y = acc[j][i] * sc + sh;
            ys[i] = 0.5f * y * (1.0f + erff(y * 0.70710678118654752f));
        }
        r.x = ys[0]; r.y = ys[1]; r.z = ys[2]; r.w = ys[3];
        float* op = out + ((size_t)b * CO + o) * HW + pix0 + ty * 4;
        *(float4*)op = r;   // warp covers 256B contiguous per o-row: STG.128 coalesced
    }
}

extern "C" void kernel_launch(void* const* d_in, const int* in_sizes, int n_in,
                              void* d_out, int out_size) {
    const float* x     = (const float*)d_in[0];
    const float* Wc    = (const float*)d_in[1];
    const float* bconv = (const float*)d_in[2];
    const float* gamma = (const float*)d_in[3];
    const float* beta  = (const float*)d_in[4];
    const float* rmean = (const float*)d_in[5];
    const float* rvar  = (const float*)d_in[6];
    float* out = (float*)d_out;

    minxj_kernel<<<B_ * C_, 256>>>(x);
    dim3 grid(CO / BN, (HW / BM) * B_);   // (6, 1568)
    gemm_bn_gelu_kernel<<<grid, 256>>>(x, Wc, bconv, gamma, beta, rmean, rvar, out);
}

// round 4
// speedup vs baseline: 1.0043x; 1.0043x over previous
#include <cuda_runtime.h>
#include <math.h>

#define B_   32
#define C_   192
#define HH   56
#define WW   56
#define HW   3136      // 56*56
#define CO   384
#define K2   384       // 2*C
#define BN_EPS 1e-5f

// scratch: xj tensor [B, C, H, W] (77 MB)
__device__ float g_xj[(size_t)B_ * C_ * HW];

// ---------------------------------------------------------------------------
// Stage 1: per-(b,c) image -> xj via parity mins.
// xj[p,q] = x[p,q] - min( min over rows r (r&1==p&1) of x[r,q],
//                         min over cols c (c&1==q&1) of x[p,c] )
// (both mins INCLUDE the element itself; this folds the max(0,.) exactly)
// ---------------------------------------------------------------------------
__global__ __launch_bounds__(256) void minxj_kernel(const float* __restrict__ x) {
    __shared__ float img[HW];
    __shared__ float cmin[2][WW];
    __shared__ float rmin[HH][2];
    const size_t bc = blockIdx.x;
    const float* xp = x + bc * HW;
    for (int i = threadIdx.x; i < HW; i += 256) img[i] = xp[i];
    __syncthreads();
    int t = threadIdx.x;
    if (t < 112) {
        int par = t / 56, q = t % 56;
        float m = 3.4e38f;
        #pragma unroll 7
        for (int r = par; r < HH; r += 2) m = fminf(m, img[r * WW + q]);
        cmin[par][q] = m;
    } else if (t < 224) {
        int t2 = t - 112;
        int par = t2 / 56, p = t2 % 56;
        float m = 3.4e38f;
        const float* row = &img[p * WW];
        #pragma unroll 7
        for (int q = par; q < WW; q += 2) m = fminf(m, row[q]);
        rmin[p][par] = m;
    }
    __syncthreads();
    float* xjp = g_xj + bc * HW;
    for (int i = threadIdx.x; i < HW; i += 256) {
        int p = i / WW, q = i - p * WW;
        float v = img[i];
        xjp[i] = v - fminf(cmin[p & 1][q], rmin[p][q & 1]);
    }
}

// ---------------------------------------------------------------------------
// Stage 2: fused per-pixel GEMM + bias + BN(inference) + exact GELU.
// out[b,o,pix] = gelu( (sum_k A[b,pix,k] * Wc[o,k] + bias[o]) * scale + shift )
//   A[:, :192] = x, A[:, 192:] = xj
// Tile: BM=64 pixels x BN=64 outs x BK=16, 256 threads, 4x4 microtile.
// ---------------------------------------------------------------------------
#define BM 64
#define BN 64
#define BK 16

__global__ __launch_bounds__(256) void gemm_bn_gelu_kernel(
    const float* __restrict__ x,  const float* __restrict__ Wc,
    const float* __restrict__ bconv, const float* __restrict__ gamma,
    const float* __restrict__ beta,  const float* __restrict__ rmean,
    const float* __restrict__ rvar,  float* __restrict__ out)
{
    __shared__ float As[BK][BM];
    __shared__ float Bs[BK][BN + 4];   // +4 pad: kills bank conflicts, keeps 16B align

    const int otile = blockIdx.x;          // 0..5
    const int mtile = blockIdx.y % 49;     // 3136/64 = 49 tiles per image (exact)
    const int b     = blockIdx.y / 49;
    const int pix0  = mtile * BM;
    const int o0    = otile * BN;

    const int tid = threadIdx.x;
    const int ty  = tid & 15;    // pixel dim (m = ty*4 + i)
    const int tx  = tid >> 4;    // output-channel dim (o = tx*4 + j)

    float acc[4][4] = {};

    const float* Abase_x  = x    + ((size_t)b * C_) * HW + pix0;
    const float* Abase_xj = g_xj + ((size_t)b * C_) * HW + pix0;

    const int la_m = tid & 63;   // A loader: m
    const int la_k = tid >> 6;   // A loader: k base (0..3), +4 per pass
    const int lb_k = tid & 15;   // B loader: k
    const int lb_o = tid >> 4;   // B loader: o base (0..15), +16 per pass

    for (int kt = 0; kt < K2; kt += BK) {
        #pragma unroll
        for (int pass = 0; pass < 4; pass++) {
            int kl = la_k + pass * 4;
            int ks = kt + kl;
            const float* src = (ks < C_) ? (Abase_x  + (size_t)ks * HW)
                                         : (Abase_xj + (size_t)(ks - C_) * HW);
            As[kl][la_m] = src[la_m];
        }
        #pragma unroll
        for (int pass = 0; pass < 4; pass++) {
            int ol = lb_o + pass * 16;
            Bs[lb_k][ol] = Wc[(size_t)(o0 + ol) * K2 + kt + lb_k];
        }
        __syncthreads();
        #pragma unroll
        for (int kk = 0; kk < BK; kk++) {
            float4 a4 = *(const float4*)&As[kk][ty * 4];
            float4 b4 = *(const float4*)&Bs[kk][tx * 4];
            float av[4] = {a4.x, a4.y, a4.z, a4.w};
            float bv[4] = {b4.x, b4.y, b4.z, b4.w};
            #pragma unroll
            for (int j = 0; j < 4; j++)
                #pragma unroll
                for (int i = 0; i < 4; i++)
                    acc[j][i] = fmaf(av[i], bv[j], acc[j][i]);
        }
        __syncthreads();
    }

    // epilogue: bias + BN fold + exact-erf GELU, vectorized stores
    #pragma unroll
    for (int j = 0; j < 4; j++) {
        const int o = o0 + tx * 4 + j;
        const float sc = gamma[o] * rsqrtf(rvar[o] + BN_EPS);
        const float sh = (bconv[o] - rmean[o]) * sc + beta[o];
        float4 r;
        float ys[4];
        #pragma unroll
        for (int i = 0; i < 4; i++) {
            float y = acc[j][i] * sc + sh;
            ys[i] = 0.5f * y * (1.0f + erff(y * 0.70710678118654752f));
        }
        r.x = ys[0]; r.y = ys[1]; r.z = ys[2]; r.w = ys[3];
        float* op = out + ((size_t)b * CO + o) * HW + pix0 + ty * 4;
        *(float4*)op = r;   // warp covers 256B contiguous per o-row: STG.128 coalesced
    }
}

extern "C" void kernel_launch(void* const* d_in, const int* in_sizes, int n_in,
                              void* d_out, int out_size) {
    const float* x     = (const float*)d_in[0];
    const float* Wc    = (const float*)d_in[1];
    const float* bconv = (const float*)d_in[2];
    const float* gamma = (const float*)d_in[3];
    const float* beta  = (const float*)d_in[4];
    const float* rmean = (const float*)d_in[5];
    const float* rvar  = (const float*)d_in[6];
    float* out = (float*)d_out;

    minxj_kernel<<<B_ * C_, 256>>>(x);
    dim3 grid(CO / BN, (HW / BM) * B_);   // (6, 1568)
    gemm_bn_gelu_kernel<<<grid, 256>>>(x, Wc, bconv, gamma, beta, rmean, rvar, out);
}

// round 6
// speedup vs baseline: 2.1795x; 2.1702x over previous
#include <cuda_runtime.h>
#include <cuda_bf16.h>
#include <math.h>
#include <stdint.h>

#define B_   32
#define C_   192
#define HH   56
#define WW   56
#define HW   3136
#define CO   384
#define K2   384
#define BN_EPS 1e-5f

__device__ float g_xj[(size_t)B_ * C_ * HW];

// ===================== Stage 1: xj via parity mins =====================
__global__ __launch_bounds__(256) void minxj_kernel(const float* __restrict__ x) {
    __shared__ float img[HW];
    __shared__ float cmin[2][WW];
    __shared__ float rmin[HH][2];
    const size_t bc = blockIdx.x;
    const float* xp = x + bc * HW;
    for (int i = threadIdx.x; i < HW; i += 256) img[i] = xp[i];
    __syncthreads();
    int t = threadIdx.x;
    if (t < 112) {
        int par = t / 56, q = t % 56;
        float m = 3.4e38f;
        #pragma unroll 7
        for (int r = par; r < HH; r += 2) m = fminf(m, img[r * WW + q]);
        cmin[par][q] = m;
    } else if (t < 224) {
        int t2 = t - 112;
        int par = t2 / 56, p = t2 % 56;
        float m = 3.4e38f;
        const float* row = &img[p * WW];
        #pragma unroll 7
        for (int q = par; q < WW; q += 2) m = fminf(m, row[q]);
        rmin[p][par] = m;
    }
    __syncthreads();
    float* xjp = g_xj + bc * HW;
    for (int i = threadIdx.x; i < HW; i += 256) {
        int p = i / WW, q = i - p * WW;
        float v = img[i];
        xjp[i] = v - fminf(cmin[p & 1][q], rmin[p][q & 1]);
    }
}

// ===================== Stage 2: mma.sync bf16 GEMM + BN + GELU =====================
// SMEM (dynamic): two buffers, each:
//   AH [32 k][136 m-bf16 stride] (272B rows, 8704B), AL same
//   BH [128 n][40 k-bf16 stride] (80B rows, 10240B), BL same
#define OFF_AH 0
#define OFF_AL 8704
#define OFF_BH 17408
#define OFF_BL 27648
#define BUFSZ  37888
#define OFF_SC 75776
#define OFF_SH 76288
#define SMEM_TOTAL 76800

__device__ __forceinline__ uint32_t smem_u32(const void* p) {
    uint32_t a;
    asm("{ .reg .u64 t; cvta.to.shared.u64 t, %1; cvt.u32.u64 %0, t; }" : "=r"(a) : "l"(p));
    return a;
}
__device__ __forceinline__ void ldsm_x4t(uint32_t* r, uint32_t a) {
    asm volatile("ldmatrix.sync.aligned.m8n8.x4.trans.shared.b16 {%0,%1,%2,%3}, [%4];"
        : "=r"(r[0]), "=r"(r[1]), "=r"(r[2]), "=r"(r[3]) : "r"(a));
}
__device__ __forceinline__ void ldsm_x4(uint32_t* r, uint32_t a) {
    asm volatile("ldmatrix.sync.aligned.m8n8.x4.shared.b16 {%0,%1,%2,%3}, [%4];"
        : "=r"(r[0]), "=r"(r[1]), "=r"(r[2]), "=r"(r[3]) : "r"(a));
}
__device__ __forceinline__ void mma_bf16(float* c, const uint32_t* a, const uint32_t* b) {
    asm volatile("mma.sync.aligned.m16n8k16.row.col.f32.bf16.bf16.f32 "
        "{%0,%1,%2,%3},{%4,%5,%6,%7},{%8,%9},{%0,%1,%2,%3};"
        : "+f"(c[0]), "+f"(c[1]), "+f"(c[2]), "+f"(c[3])
        : "r"(a[0]), "r"(a[1]), "r"(a[2]), "r"(a[3]), "r"(b[0]), "r"(b[1]));
}
__device__ __forceinline__ void split4(float4 f, uint32_t& h01, uint32_t& h23,
                                       uint32_t& l01, uint32_t& l23) {
    __nv_bfloat162 a = __floats2bfloat162_rn(f.x, f.y);
    __nv_bfloat162 b = __floats2bfloat162_rn(f.z, f.w);
    float r0 = f.x - __bfloat162float(a.x);
    float r1 = f.y - __bfloat162float(a.y);
    float r2 = f.z - __bfloat162float(b.x);
    float r3 = f.w - __bfloat162float(b.y);
    __nv_bfloat162 c = __floats2bfloat162_rn(r0, r1);
    __nv_bfloat162 d = __floats2bfloat162_rn(r2, r3);
    h01 = *(uint32_t*)&a; h23 = *(uint32_t*)&b;
    l01 = *(uint32_t*)&c; l23 = *(uint32_t*)&d;
}
#define STS8(addr, a, b) asm volatile("st.shared.v2.b32 [%0], {%1,%2};" :: "r"(addr), "r"(a), "r"(b) : "memory")

__global__ __launch_bounds__(256, 1) void gemm_mma_kernel(
    const float* __restrict__ x,  const float* __restrict__ Wc,
    const float* __restrict__ bconv, const float* __restrict__ gamma,
    const float* __restrict__ beta,  const float* __restrict__ rmean,
    const float* __restrict__ rvar,  float* __restrict__ out)
{
    extern __shared__ char sm[];
    const uint32_t sbase = smem_u32(sm);
    const int tid = threadIdx.x, wid = tid >> 5, lid = tid & 31;
    const int o0 = blockIdx.x * 128;
    const int g0 = blockIdx.y * 128;
    const int warp_m = wid >> 2;     // 0..1
    const int warp_n = wid & 3;      // 0..3

    float* scp = (float*)(sm + OFF_SC);
    float* shp = (float*)(sm + OFF_SH);
    if (tid < 128) {
        int o = o0 + tid;
        float sc = gamma[o] * rsqrtf(rvar[o] + BN_EPS);
        scp[tid] = sc;
        shp[tid] = (bconv[o] - rmean[o]) * sc + beta[o];
    }

    // ---- loader index precompute ----
    const int a_kj = wid << 2;              // warp handles k = a_kj..a_kj+3 within chunk
    const int a_m  = lid << 2;              // 4 consecutive m per lane
    const int a_g  = g0 + a_m;
    const int a_b  = a_g / HW;
    const int a_p  = a_g - a_b * HW;        // float4-safe (boundary multiple of 4)
    const int b_n  = tid >> 1, b_h = tid & 1;

    float4 av[4], bv[4];
    // prefetch chunk 0 (channels 0..31 from x)
    {
        const float* ap = x + ((size_t)(a_b * C_ + a_kj)) * HW + a_p;
        #pragma unroll
        for (int j = 0; j < 4; j++) av[j] = *(const float4*)(ap + (size_t)j * HW);
        const float* bp = Wc + (size_t)(o0 + b_n) * K2 + b_h * 16;
        #pragma unroll
        for (int i = 0; i < 4; i++) bv[i] = *(const float4*)(bp + i * 4);
    }

    float acc[4][4][4];
    #pragma unroll
    for (int i = 0; i < 4; i++)
        #pragma unroll
        for (int j = 0; j < 4; j++)
            #pragma unroll
            for (int e = 0; e < 4; e++) acc[i][j][e] = 0.f;

    // ldmatrix lane-address components
    const uint32_t a_row  = (uint32_t)((lid & 7) + ((lid >> 4) << 3));           // k row
    const uint32_t a_moff = (uint32_t)((warp_m * 64 + (((lid >> 3) & 1) << 3)) * 2);
    const uint32_t b_row  = (uint32_t)(warp_n * 32 + (lid & 7) + ((lid >> 4) << 3));
    const uint32_t b_koff = (uint32_t)(((lid >> 3) & 1) * 16);

    for (int c = 0; c < 12; c++) {
        const uint32_t buf = sbase + (uint32_t)(c & 1) * BUFSZ;
        // ---- STS this chunk (convert fp32 -> bf16 hi/lo) ----
        #pragma unroll
        for (int j = 0; j < 4; j++) {
            uint32_t h01, h23, l01, l23;
            split4(av[j], h01, h23, l01, l23);
            uint32_t ad = buf + OFF_AH + (uint32_t)(a_kj + j) * 272u + (uint32_t)a_m * 2u;
            STS8(ad, h01, h23);
            STS8(ad + (OFF_AL - OFF_AH), l01, l23);
        }
        #pragma unroll
        for (int i = 0; i < 4; i++) {
            uint32_t h01, h23, l01, l23;
            split4(bv[i], h01, h23, l01, l23);
            uint32_t bd = buf + OFF_BH + (uint32_t)b_n * 80u + (uint32_t)b_h * 32u + (uint32_t)i * 8u;
            STS8(bd, h01, h23);
            STS8(bd + (OFF_BL - OFF_BH), l01, l23);
        }
        __syncthreads();

        // ---- prefetch next chunk ----
        if (c + 1 < 12) {
            int cn = c + 1;
            const float* src; int ch0;
            if (cn < 6) { src = x; ch0 = cn * 32; } else { src = g_xj; ch0 = cn * 32 - 192; }
            const float* ap = src + ((size_t)(a_b * C_ + ch0 + a_kj)) * HW + a_p;
            #pragma unroll
            for (int j = 0; j < 4; j++) av[j] = *(const float4*)(ap + (size_t)j * HW);
            const float* bp = Wc + (size_t)(o0 + b_n) * K2 + cn * 32 + b_h * 16;
            #pragma unroll
            for (int i = 0; i < 4; i++) bv[i] = *(const float4*)(bp + i * 4);
        }

        // ---- MMA on this chunk: 2 k16-steps x (AhBh + AlBh + AhBl) ----
        #pragma unroll
        for (int s = 0; s < 2; s++) {
            uint32_t ah[4][4], al[4][4], bh[2][4], bl[2][4];
            const uint32_t ab = buf + OFF_AH + ((uint32_t)(s * 16) + a_row) * 272u + a_moff;
            #pragma unroll
            for (int mf = 0; mf < 4; mf++) {
                ldsm_x4t(ah[mf], ab + (uint32_t)mf * 32u);
                ldsm_x4t(al[mf], ab + (OFF_AL - OFF_AH) + (uint32_t)mf * 32u);
            }
            const uint32_t bb = buf + OFF_BH + b_row * 80u + (uint32_t)(s * 32) + b_koff;
            #pragma unroll
            for (int q = 0; q < 2; q++) {
                ldsm_x4(bh[q], bb + (uint32_t)q * (16u * 80u));
                ldsm_x4(bl[q], bb + (OFF_BL - OFF_BH) + (uint32_t)q * (16u * 80u));
            }
            #pragma unroll
            for (int mf = 0; mf < 4; mf++) {
                #pragma unroll
                for (int nf = 0; nf < 4; nf++) {
                    const uint32_t* bhp = &bh[nf >> 1][(nf & 1) * 2];
                    const uint32_t* blp = &bl[nf >> 1][(nf & 1) * 2];
                    mma_bf16(acc[mf][nf], ah[mf], bhp);
                    mma_bf16(acc[mf][nf], al[mf], bhp);
                    mma_bf16(acc[mf][nf], ah[mf], blp);
                }
            }
        }
        __syncthreads();
    }

    // ---- epilogue: BN + exact GELU, direct STG (32B sectors per lane-quad) ----
    #pragma unroll
    for (int mf = 0; mf < 4; mf++) {
        const int ml = warp_m * 64 + mf * 16 + (lid >> 2);
        #pragma unroll
        for (int half = 0; half < 2; half++) {
            int g = g0 + ml + half * 8;
            int bb = g / HW, p = g - bb * HW;
            float* orow = out + ((size_t)bb * CO + o0) * HW + p;
            #pragma unroll
            for (int nf = 0; nf < 4; nf++) {
                #pragma unroll
                for (int e = 0; e < 2; e++) {
                    int n = warp_n * 32 + nf * 8 + (lid & 3) * 2 + e;
                    float y = acc[mf][nf][half * 2 + e] * scp[n] + shp[n];
                    y = 0.5f * y * (1.0f + erff(y * 0.70710678118654752f));
                    orow[(size_t)n * HW] = y;
                }
            }
        }
    }
}

extern "C" void kernel_launch(void* const* d_in, const int* in_sizes, int n_in,
                              void* d_out, int out_size) {
    const float* x     = (const float*)d_in[0];
    const float* Wc    = (const float*)d_in[1];
    const float* bconv = (const float*)d_in[2];
    const float* gamma = (const float*)d_in[3];
    const float* beta  = (const float*)d_in[4];
    const float* rmean = (const float*)d_in[5];
    const float* rvar  = (const float*)d_in[6];
    float* out = (float*)d_out;

    minxj_kernel<<<B_ * C_, 256>>>(x);

    cudaFuncSetAttribute(gemm_mma_kernel,
                         cudaFuncAttributeMaxDynamicSharedMemorySize, SMEM_TOTAL);
    dim3 grid(CO / 128, HW * B_ / 128);   // (3, 784)
    gemm_mma_kernel<<<grid, 256, SMEM_TOTAL>>>(x, Wc, bconv, gamma, beta,
                                               rmean, rvar, out);
}